// round 3
// baseline (speedup 1.0000x reference)
#include <cuda_runtime.h>
#include <cstdint>

namespace qef {

constexpr int E_ = 8, T_ = 1024, DIN = 2048, DOUT = 8192;
constexpr int NKC = DIN / 32;           // 64 k-chunks of 32

// -------- scratch (fragment-ordered operands) --------
// B: [e][ntile(n/8)][kc][256B block]  (256B = 32 lanes x 8B)
// A: [e][mtile(m/16)][kc][lvl(hi/lo)][512B block] (512B = 32 lanes x 16B)
__device__ __align__(16) unsigned char g_brep[(size_t)E_ * (DOUT / 8) * NKC * 256];
__device__ __align__(16) unsigned char g_arep[(size_t)E_ * (T_ / 16) * NKC * 2 * 512];

__device__ __forceinline__ uint32_t pack4(int a, int b, int c, int d) {
  return (uint32_t)(a & 0xff) | ((uint32_t)(b & 0xff) << 8) |
         ((uint32_t)(c & 0xff) << 16) | ((uint32_t)d << 24);
}

// ---------------- repack weights: int32 -> s8, fragment order ----------------
__global__ void __launch_bounds__(256) repack_b(const int* __restrict__ wq) {
  const int t = blockIdx.x * 256 + threadIdx.x;     // [0, 8*8192*64)
  const int kc = t & 63;
  const int n  = (t >> 6) & 8191;
  const int e  = t >> 19;
  const int4* src = reinterpret_cast<const int4*>(
      wq + ((size_t)e * DOUT + n) * DIN + kc * 32);
  int4 v[8];
#pragma unroll
  for (int i = 0; i < 8; ++i) v[i] = src[i];        // v[i] = k (4i..4i+3)
  // word(g,j) = bytes for kk = j*16 + g*4 .. +3  => v[j*4+g]
  uint32_t w[8];
#pragma unroll
  for (int g = 0; g < 4; ++g)
#pragma unroll
    for (int j = 0; j < 2; ++j) {
      int4 q = v[j * 4 + g];
      w[g * 2 + j] = pack4(q.x, q.y, q.z, q.w);
    }
  unsigned char* dst = g_brep +
      ((((size_t)e * (DOUT / 8) + (n >> 3)) * NKC + kc) << 8) + (n & 7) * 32;
  reinterpret_cast<uint4*>(dst)[0] = make_uint4(w[0], w[1], w[2], w[3]);
  reinterpret_cast<uint4*>(dst)[1] = make_uint4(w[4], w[5], w[6], w[7]);
}

// ---------------- repack input: fp32 -> dual s8 (x ~ a/16 + b/4096) ----------
__global__ void __launch_bounds__(256) repack_a(const float* __restrict__ in) {
  const int t = blockIdx.x * 256 + threadIdx.x;     // [0, 8*1024*64)
  const int kc = t & 63;
  const int m  = (t >> 6) & 1023;
  const int e  = t >> 16;
  const float4* src = reinterpret_cast<const float4*>(
      in + ((size_t)e * T_ + m) * DIN + kc * 32);
  int ah[32], bl[32];
#pragma unroll
  for (int i = 0; i < 8; ++i) {
    float4 x4 = src[i];
    float xs[4] = {x4.x, x4.y, x4.z, x4.w};
#pragma unroll
    for (int c = 0; c < 4; ++c) {
      float x = xs[c];
      int a = __float2int_rn(x * 16.0f);
      a = max(-127, min(127, a));
      float r = x - (float)a * 0.0625f;
      int b = __float2int_rn(r * 4096.0f);
      b = max(-127, min(127, b));
      ah[i * 4 + c] = a;
      bl[i * 4 + c] = b;
    }
  }
  const int r = m & 15;
  const uint32_t base_off = (uint32_t)(r & 7) * 64 + ((r >= 8) ? 4u : 0u);
  unsigned char* blk = g_arep +
      (((((size_t)e * (T_ / 16) + (m >> 4)) * NKC + kc) * 2) << 9);
#pragma unroll
  for (int g = 0; g < 4; ++g)
#pragma unroll
    for (int j = 0; j < 2; ++j) {
      const int kkb = j * 16 + g * 4;
      const uint32_t off = base_off + g * 16 + j * 8;
      *reinterpret_cast<uint32_t*>(blk + off) =
          pack4(ah[kkb], ah[kkb + 1], ah[kkb + 2], ah[kkb + 3]);
      *reinterpret_cast<uint32_t*>(blk + 512 + off) =
          pack4(bl[kkb], bl[kkb + 1], bl[kkb + 2], bl[kkb + 3]);
    }
}

// ---------------- GEMM: 128x128 CTA, 8 warps (4m x 2n), dual-int8 mma -------
constexpr int STAGES = 4;
constexpr int A_STAGE = 8 * 2 * 2 * 512;   // 16KB: [mt(8)][kc(2)][lvl(2)]x512
constexpr int B_STAGE = 16 * 2 * 256;      // 8KB : [nt(16)][kc(2)]x256
constexpr int STAGE_BYTES = A_STAGE + B_STAGE;          // 24KB
constexpr int SMEM_TOTAL = STAGES * STAGE_BYTES;        // 96KB

__device__ __forceinline__ uint32_t cvta_smem(const void* p) {
  uint32_t a;
  asm("{ .reg .u64 t; cvta.to.shared.u64 t, %1; cvt.u32.u64 %0, t; }" : "=r"(a) : "l"(p));
  return a;
}
__device__ __forceinline__ void cp16(uint32_t sdst, const void* gsrc) {
  asm volatile("cp.async.cg.shared.global [%0], [%1], 16;" :: "r"(sdst), "l"(gsrc));
}
__device__ __forceinline__ void cp_commit() {
  asm volatile("cp.async.commit_group;" ::: "memory");
}
__device__ __forceinline__ void cp_wait2() {
  asm volatile("cp.async.wait_group 2;" ::: "memory");
}
__device__ __forceinline__ void lds128(uint32_t* r, uint32_t a) {
  asm volatile("ld.shared.v4.b32 {%0,%1,%2,%3}, [%4];"
               : "=r"(r[0]), "=r"(r[1]), "=r"(r[2]), "=r"(r[3]) : "r"(a));
}
__device__ __forceinline__ void lds64(uint32_t* r, uint32_t a) {
  asm volatile("ld.shared.v2.b32 {%0,%1}, [%2];" : "=r"(r[0]), "=r"(r[1]) : "r"(a));
}
__device__ __forceinline__ void imma(int* d, const uint32_t* a, const uint32_t* b) {
  asm volatile(
      "mma.sync.aligned.m16n8k32.row.col.s32.s8.s8.s32 "
      "{%0,%1,%2,%3}, {%4,%5,%6,%7}, {%8,%9}, {%0,%1,%2,%3};"
      : "+r"(d[0]), "+r"(d[1]), "+r"(d[2]), "+r"(d[3])
      : "r"(a[0]), "r"(a[1]), "r"(a[2]), "r"(a[3]), "r"(b[0]), "r"(b[1]));
}

__global__ void __launch_bounds__(256, 1)
gemm(const float* __restrict__ sc, float* __restrict__ out) {
  extern __shared__ unsigned char smem[];
  const uint32_t sbase = cvta_smem(smem);
  const int tid  = threadIdx.x;
  const int wid  = tid >> 5;
  const int lane = tid & 31;

  // bid: m fastest within expert (co-resident CTAs share B tiles in L2)
  const int bid = blockIdx.x;
  const int e   = bid >> 9;
  const int m   = bid & 7;          // 8 m-tiles of 128
  const int n   = (bid >> 3) & 63;  // 64 n-tiles of 128
  const int mt0 = m * 8;            // global 16-row mtile base
  const int nt0 = n * 16;           // global 8-col ntile base

  const int wm = wid & 3;           // warp M: 4 x 32 rows
  const int wn = wid >> 2;          // warp N: 2 x 64 cols

  const unsigned char* abase = g_arep + (((size_t)e * (T_ / 16) + mt0) * NKC * 2) * 512;
  const unsigned char* bbase = g_brep + (((size_t)e * (DOUT / 8) + nt0) * NKC) * 256;

  // per-stage async copy: 1536 x 16B units (A: 1024, B: 512)
  auto issue_stage = [&](int ks, int st) {
    const int kc0 = ks * 2;
    const uint32_t sb = sbase + st * STAGE_BYTES;
#pragma unroll
    for (int i = 0; i < 6; ++i) {
      const int u = tid + i * 256;
      if (u < 1024) {
        const int chunk = u >> 5, pos = u & 31;         // chunk = mt*4+kc*2+lvl
        const int mt = chunk >> 2, kc = (chunk >> 1) & 1, lvl = chunk & 1;
        const unsigned char* g = abase +
            (((size_t)mt * NKC + (kc0 + kc)) * 2 + lvl) * 512 + pos * 16;
        cp16(sb + u * 16, g);
      } else {
        const int u2 = u - 1024;
        const int chunk = u2 >> 4, pos = u2 & 15;       // chunk = nt*2+kc
        const int nt = chunk >> 1, kc = chunk & 1;
        const unsigned char* g = bbase +
            ((size_t)nt * NKC + (kc0 + kc)) * 256 + pos * 16;
        cp16(sb + A_STAGE + u2 * 16, g);
      }
    }
    cp_commit();
  };

  int acc[2][8][2][4];
#pragma unroll
  for (int mi = 0; mi < 2; ++mi)
#pragma unroll
    for (int ni = 0; ni < 8; ++ni)
#pragma unroll
      for (int l = 0; l < 2; ++l)
#pragma unroll
        for (int c = 0; c < 4; ++c) acc[mi][ni][l][c] = 0;

  const int NKS = NKC / 2;  // 32 stages of k=64
  issue_stage(0, 0);
  issue_stage(1, 1);
  issue_stage(2, 2);

  for (int ks = 0; ks < NKS; ++ks) {
    cp_wait2();
    __syncthreads();
    const uint32_t sb = sbase + (ks & 3) * STAGE_BYTES;
#pragma unroll
    for (int kc = 0; kc < 2; ++kc) {
      uint32_t af[2][2][4], bf[8][2];
#pragma unroll
      for (int mi = 0; mi < 2; ++mi) {
        const int mt_local = wm * 2 + mi;
#pragma unroll
        for (int l = 0; l < 2; ++l)
          lds128(af[mi][l], sb + ((mt_local * 2 + kc) * 2 + l) * 512 + lane * 16);
      }
#pragma unroll
      for (int ni = 0; ni < 8; ++ni) {
        const int nt_local = wn * 8 + ni;
        lds64(bf[ni], sb + A_STAGE + (nt_local * 2 + kc) * 256 + lane * 8);
      }
#pragma unroll
      for (int mi = 0; mi < 2; ++mi)
#pragma unroll
        for (int ni = 0; ni < 8; ++ni) {
          imma(acc[mi][ni][0], af[mi][0], bf[ni]);
          imma(acc[mi][ni][1], af[mi][1], bf[ni]);
        }
    }
    if (ks + 3 < NKS) issue_stage(ks + 3, (ks + 3) & 3);
  }

  // epilogue: out = s * (accH/16 + accL/4096), combined in double
  const double s  = (double)sc[e];
  const double c1 = s * 0.0625;
  const double c2 = s * 0.000244140625;
  const int r_in  = lane >> 2;
  const int c_in  = (lane & 3) * 2;
#pragma unroll
  for (int mi = 0; mi < 2; ++mi) {
    const int row0 = m * 128 + wm * 32 + mi * 16 + r_in;
#pragma unroll
    for (int ni = 0; ni < 8; ++ni) {
      const int col = n * 128 + wn * 64 + ni * 8 + c_in;
      const int* h = acc[mi][ni][0];
      const int* l = acc[mi][ni][1];
      float2 v0, v1;
      v0.x = (float)((double)h[0] * c1 + (double)l[0] * c2);
      v0.y = (float)((double)h[1] * c1 + (double)l[1] * c2);
      v1.x = (float)((double)h[2] * c1 + (double)l[2] * c2);
      v1.y = (float)((double)h[3] * c1 + (double)l[3] * c2);
      float* o0 = out + ((size_t)e * T_ + row0) * DOUT + col;
      *reinterpret_cast<float2*>(o0) = v0;
      *reinterpret_cast<float2*>(o0 + 8 * DOUT) = v1;
    }
  }
}

}  // namespace qef

extern "C" void kernel_launch(void* const* d_in, const int* in_sizes, int n_in,
                              void* d_out, int out_size) {
  const float* in  = (const float*)d_in[0];
  const int*   wq  = (const int*)d_in[1];
  const float* sc  = (const float*)d_in[2];
  float*       out = (float*)d_out;

  qef::repack_b<<<(8 * 8192 * 64) / 256, 256>>>(wq);
  qef::repack_a<<<(8 * 1024 * 64) / 256, 256>>>(in);

  static bool attr_set = false;
  if (!attr_set) {
    cudaFuncSetAttribute(qef::gemm, cudaFuncAttributeMaxDynamicSharedMemorySize,
                         qef::SMEM_TOTAL);
    attr_set = true;
  }
  qef::gemm<<<8 * 8 * 64, 256, qef::SMEM_TOTAL>>>(sc, out);
}

// round 4
// speedup vs baseline: 2.8186x; 2.8186x over previous
#include <cuda_runtime.h>
#include <cuda_fp16.h>
#include <cstdint>

namespace qef {

constexpr int E_ = 8, T_ = 1024, DIN = 2048, DOUT = 8192;
constexpr int NKS16 = DIN / 16;   // 128 k-steps of 16
constexpr int NKC   = DIN / 32;   // 64 repack chunks of 32

// -------- scratch, fragment-ordered for mma.m16n8k16 --------
// B: [e][ntile(n/8)=1024][ks16(128)][256B]   (256B = 32 lanes x 8B: {b0,b1})
// A: [e][mtile(m/16)=64][ks16(128)][lvl(2)][512B] (512B = 32 lanes x 16B: {a0..a3})
__device__ __align__(16) unsigned char g_brep[(size_t)E_ * 1024 * 128 * 256];
__device__ __align__(16) unsigned char g_arep[(size_t)E_ * 64 * 128 * 2 * 512];

__device__ __forceinline__ uint32_t hpack(__half lo, __half hi) {
  return (uint32_t)__half_as_ushort(lo) | ((uint32_t)__half_as_ushort(hi) << 16);
}

// ---------------- repack weights: int32 -> f16 fragments ----------------
// thread = (e, n, kc) ; kc = 32-k chunk
__global__ void __launch_bounds__(256) repack_b(const int* __restrict__ wq) {
  const int t  = blockIdx.x * 256 + threadIdx.x;   // [0, 8*8192*64)
  const int kc = t & 63;
  const int n  = (t >> 6) & 8191;
  const int e  = t >> 19;
  const int4* src = reinterpret_cast<const int4*>(
      wq + ((size_t)e * DOUT + n) * DIN + kc * 32);
  int v[32];
#pragma unroll
  for (int i = 0; i < 8; ++i) {
    int4 q = src[i];
    v[i * 4 + 0] = q.x; v[i * 4 + 1] = q.y; v[i * 4 + 2] = q.z; v[i * 4 + 3] = q.w;
  }
  // For each k16 step s: lane (n&7)*4+j holds {B[k],B[k+1]} and {B[k+8],B[k+9]},
  // k = 2j (row.col B-fragment mapping)
#pragma unroll
  for (int s = 0; s < 2; ++s) {
    unsigned char* blk = g_brep +
        ((((size_t)e * 1024 + (n >> 3)) * 128 + kc * 2 + s) << 8);
#pragma unroll
    for (int j = 0; j < 4; ++j) {
      const int kb = s * 16 + 2 * j;
      const uint32_t w0 = hpack(__int2half_rn(v[kb]),     __int2half_rn(v[kb + 1]));
      const uint32_t w1 = hpack(__int2half_rn(v[kb + 8]), __int2half_rn(v[kb + 9]));
      *reinterpret_cast<uint2*>(blk + ((n & 7) * 4 + j) * 8) = make_uint2(w0, w1);
    }
  }
}

// ---------------- repack input: fp32 -> dual f16 (x = hi + lo) ----------------
__global__ void __launch_bounds__(256) repack_a(const float* __restrict__ in) {
  const int t  = blockIdx.x * 256 + threadIdx.x;   // [0, 8*1024*64)
  const int kc = t & 63;
  const int m  = (t >> 6) & 1023;
  const int e  = t >> 16;
  const float4* src = reinterpret_cast<const float4*>(
      in + ((size_t)e * T_ + m) * DIN + kc * 32);
  __half h[32], l[32];
#pragma unroll
  for (int i = 0; i < 8; ++i) {
    float4 x4 = src[i];
    float xs[4] = {x4.x, x4.y, x4.z, x4.w};
#pragma unroll
    for (int c = 0; c < 4; ++c) {
      __half hh = __float2half_rn(xs[c]);
      h[i * 4 + c] = hh;
      l[i * 4 + c] = __float2half_rn(xs[c] - __half2float(hh));
    }
  }
  const int r  = m & 15;
  const int mt = m >> 4;
  // A-fragment: lane (r&7)*4+j ; a0/a1 at bytes 0-7 (k low), a2/a3 at 8-15 (k+8).
  // r<8 -> a0/a2 (bytes +0), r>=8 -> a1/a3 (bytes +4).
  const uint32_t lbase = (uint32_t)((r & 7) * 4) * 16 + ((r >= 8) ? 4u : 0u);
#pragma unroll
  for (int s = 0; s < 2; ++s) {
#pragma unroll
    for (int lvl = 0; lvl < 2; ++lvl) {
      const __half* vv = lvl ? l : h;
      unsigned char* blk = g_arep +
          (((((size_t)e * 64 + mt) * 128 + kc * 2 + s) * 2 + lvl) << 9);
#pragma unroll
      for (int j = 0; j < 4; ++j) {
        const int kb = s * 16 + 2 * j;
        const uint32_t off = lbase + j * 16;
        *reinterpret_cast<uint32_t*>(blk + off) =
            hpack(vv[kb], vv[kb + 1]);
        *reinterpret_cast<uint32_t*>(blk + off + 8) =
            hpack(vv[kb + 8], vv[kb + 9]);
      }
    }
  }
}

// ---------------- GEMM: 128x128 CTA, 16 warps (4m x 4n), dual-f16 HMMA -------
constexpr int STAGES = 4;
constexpr int A_STAGE = 8 * 2 * 2 * 512;   // 16KB: [mt(8)][ks(2)][lvl(2)]x512
constexpr int B_STAGE = 16 * 2 * 256;      // 8KB : [nt(16)][ks(2)]x256
constexpr int STAGE_BYTES = A_STAGE + B_STAGE;      // 24KB
constexpr int SMEM_TOTAL  = STAGES * STAGE_BYTES;   // 96KB

__device__ __forceinline__ uint32_t cvta_smem(const void* p) {
  uint32_t a;
  asm("{ .reg .u64 t; cvta.to.shared.u64 t, %1; cvt.u32.u64 %0, t; }" : "=r"(a) : "l"(p));
  return a;
}
__device__ __forceinline__ void cp16(uint32_t sdst, const void* gsrc) {
  asm volatile("cp.async.cg.shared.global [%0], [%1], 16;" :: "r"(sdst), "l"(gsrc));
}
__device__ __forceinline__ void cp_commit() {
  asm volatile("cp.async.commit_group;" ::: "memory");
}
__device__ __forceinline__ void cp_wait2() {
  asm volatile("cp.async.wait_group 2;" ::: "memory");
}
__device__ __forceinline__ void lds128(uint32_t* r, uint32_t a) {
  asm volatile("ld.shared.v4.b32 {%0,%1,%2,%3}, [%4];"
               : "=r"(r[0]), "=r"(r[1]), "=r"(r[2]), "=r"(r[3]) : "r"(a));
}
__device__ __forceinline__ void lds64(uint32_t* r, uint32_t a) {
  asm volatile("ld.shared.v2.b32 {%0,%1}, [%2];" : "=r"(r[0]), "=r"(r[1]) : "r"(a));
}
__device__ __forceinline__ void hmma(float* d, const uint32_t* a, const uint32_t* b) {
  asm volatile(
      "mma.sync.aligned.m16n8k16.row.col.f32.f16.f16.f32 "
      "{%0,%1,%2,%3}, {%4,%5,%6,%7}, {%8,%9}, {%0,%1,%2,%3};"
      : "+f"(d[0]), "+f"(d[1]), "+f"(d[2]), "+f"(d[3])
      : "r"(a[0]), "r"(a[1]), "r"(a[2]), "r"(a[3]), "r"(b[0]), "r"(b[1]));
}

__global__ void __launch_bounds__(512, 1)
gemm(const float* __restrict__ sc, float* __restrict__ out) {
  extern __shared__ unsigned char smem[];
  const uint32_t sbase = cvta_smem(smem);
  const int tid  = threadIdx.x;
  const int wid  = tid >> 5;
  const int lane = tid & 31;

  const int bid = blockIdx.x;
  const int e   = bid >> 9;
  const int m   = bid & 7;          // 8 m-tiles of 128 (fast: share B in L2)
  const int n   = (bid >> 3) & 63;  // 64 n-tiles of 128
  const int mt0 = m * 8;
  const int nt0 = n * 16;

  const int wm = wid & 3;           // 4 x 32 rows
  const int wn = wid >> 2;          // 4 x 32 cols

  const unsigned char* abase = g_arep + ((size_t)(e * 64 + mt0) * 128 * 2) * 512;
  const unsigned char* bbase = g_brep + ((size_t)(e * 1024 + nt0) * 128) * 256;

  // stage = 2 k16-steps (K=32). A: 1024 16B units, B: 512 units.
  auto issue_stage = [&](int ks, int st) {
    const int ksg0 = ks * 2;
    const uint32_t sb = sbase + st * STAGE_BYTES;
#pragma unroll
    for (int i = 0; i < 3; ++i) {
      const int u = tid + i * 512;
      if (u < 1024) {
        const int chunk = u >> 5, pos = u & 31;     // chunk = mt*4 + kstep*2 + lvl
        const int mt = chunk >> 2, kstep = (chunk >> 1) & 1, lvl = chunk & 1;
        const unsigned char* g = abase +
            (((size_t)mt * 128 + ksg0 + kstep) * 2 + lvl) * 512 + pos * 16;
        cp16(sb + u * 16, g);
      } else {
        const int u2 = u - 1024;
        const int chunk = u2 >> 4, pos = u2 & 15;   // chunk = nt*2 + kstep
        const int nt = chunk >> 1, kstep = chunk & 1;
        const unsigned char* g = bbase +
            ((size_t)nt * 128 + ksg0 + kstep) * 256 + pos * 16;
        cp16(sb + A_STAGE + u2 * 16, g);
      }
    }
    cp_commit();
  };

  float acc[2][4][4];
#pragma unroll
  for (int mi = 0; mi < 2; ++mi)
#pragma unroll
    for (int ni = 0; ni < 4; ++ni)
#pragma unroll
      for (int c = 0; c < 4; ++c) acc[mi][ni][c] = 0.0f;

  const int NKS = NKS16 / 2;  // 64 stages of K=32
  issue_stage(0, 0);
  issue_stage(1, 1);
  issue_stage(2, 2);

  for (int ks = 0; ks < NKS; ++ks) {
    cp_wait2();
    __syncthreads();
    const uint32_t sb = sbase + (ks & 3) * STAGE_BYTES;
#pragma unroll
    for (int kstep = 0; kstep < 2; ++kstep) {
      uint32_t af[2][2][4], bf[4][2];
#pragma unroll
      for (int mi = 0; mi < 2; ++mi) {
        const int mt_local = wm * 2 + mi;
#pragma unroll
        for (int lvl = 0; lvl < 2; ++lvl)
          lds128(af[mi][lvl],
                 sb + ((mt_local * 2 + kstep) * 2 + lvl) * 512 + lane * 16);
      }
#pragma unroll
      for (int ni = 0; ni < 4; ++ni) {
        const int nt_local = wn * 4 + ni;
        lds64(bf[ni], sb + A_STAGE + (nt_local * 2 + kstep) * 256 + lane * 8);
      }
#pragma unroll
      for (int mi = 0; mi < 2; ++mi)
#pragma unroll
        for (int ni = 0; ni < 4; ++ni) {
          hmma(acc[mi][ni], af[mi][0], bf[ni]);   // hi pass
          hmma(acc[mi][ni], af[mi][1], bf[ni]);   // lo pass (same fp32 acc)
        }
    }
    if (ks + 3 < NKS) issue_stage(ks + 3, (ks + 3) & 3);
  }

  // ---- epilogue: out = s * acc ----
  const float s = sc[e];
  const int r_in = lane >> 2;
  const int c_in = (lane & 3) * 2;
#pragma unroll
  for (int mi = 0; mi < 2; ++mi) {
    const int row0 = m * 128 + wm * 32 + mi * 16 + r_in;
#pragma unroll
    for (int ni = 0; ni < 4; ++ni) {
      const int col = n * 128 + wn * 32 + ni * 8 + c_in;
      float* o0 = out + ((size_t)e * T_ + row0) * DOUT + col;
      float2 v0 = make_float2(acc[mi][ni][0] * s, acc[mi][ni][1] * s);
      float2 v1 = make_float2(acc[mi][ni][2] * s, acc[mi][ni][3] * s);
      *reinterpret_cast<float2*>(o0) = v0;
      *reinterpret_cast<float2*>(o0 + 8 * DOUT) = v1;
    }
  }
}

}  // namespace qef

extern "C" void kernel_launch(void* const* d_in, const int* in_sizes, int n_in,
                              void* d_out, int out_size) {
  const float* in  = (const float*)d_in[0];
  const int*   wq  = (const int*)d_in[1];
  const float* sc  = (const float*)d_in[2];
  float*       out = (float*)d_out;

  qef::repack_b<<<(8 * 8192 * 64) / 256, 256>>>(wq);
  qef::repack_a<<<(8 * 1024 * 64) / 256, 256>>>(in);

  static bool attr_set = false;
  if (!attr_set) {
    cudaFuncSetAttribute(qef::gemm, cudaFuncAttributeMaxDynamicSharedMemorySize,
                         qef::SMEM_TOTAL);
    attr_set = true;
  }
  qef::gemm<<<8 * 8 * 64, 512, qef::SMEM_TOTAL>>>(sc, out);
}